// round 5
// baseline (speedup 1.0000x reference)
#include <cuda_runtime.h>
#include <cuda_bf16.h>
#include <cstdint>

#define BATCH 8
#define SEQ   2048
#define DIM   512
#define TOK   (BATCH*SEQ)          // 16384

typedef __nv_bfloat16 bf16;

// ---------------------------------------------------------------------------
// Scratch (__device__ globals: allocation-guard safe)
// ---------------------------------------------------------------------------
__device__ bf16  g_Xh[(size_t)TOK * DIM],  g_Xl[(size_t)TOK * DIM];
__device__ bf16  g_WTh[3][DIM * DIM],      g_WTl[3][DIM * DIM];   // W^T hi/lo
__device__ bf16  g_Qh[(size_t)TOK * DIM],  g_Ql[(size_t)TOK * DIM];
__device__ bf16  g_Kh[(size_t)TOK * DIM],  g_Kl[(size_t)TOK * DIM];
__device__ bf16  g_Vth[(size_t)DIM * TOK], g_Vtl[(size_t)DIM * TOK]; // V^T [512,16384]
__device__ float g_P [(size_t)BATCH * SEQ * SEQ];
__device__ bf16  g_Ph[(size_t)BATCH * SEQ * SEQ], g_Pl[(size_t)BATCH * SEQ * SEQ];

// ---------------------------------------------------------------------------
// Baseline-PTX helpers (sm_80+: valid for compute_103 target)
// ---------------------------------------------------------------------------
__device__ __forceinline__ uint32_t s2u(const void* p) {
    uint32_t a;
    asm("{ .reg .u64 t; cvta.to.shared.u64 t, %1; cvt.u32.u64 %0, t; }" : "=r"(a) : "l"(p));
    return a;
}
__device__ __forceinline__ void cp16(uint32_t saddr, const bf16* g) {
    asm volatile("cp.async.cg.shared.global [%0], [%1], 16;"
                 :: "r"(saddr), "l"(__cvta_generic_to_global(g)) : "memory");
}
__device__ __forceinline__ void cp_commit() {
    asm volatile("cp.async.commit_group;" ::: "memory");
}
template <int N>
__device__ __forceinline__ void cp_wait() {
    asm volatile("cp.async.wait_group %0;" :: "n"(N) : "memory");
}
__device__ __forceinline__ void ldsm4(uint32_t* d, uint32_t a) {
    asm volatile("ldmatrix.sync.aligned.m8n8.x4.shared.b16 {%0,%1,%2,%3}, [%4];"
                 : "=r"(d[0]), "=r"(d[1]), "=r"(d[2]), "=r"(d[3]) : "r"(a));
}
__device__ __forceinline__ void mma16816(float* c, const uint32_t* a, const uint32_t* b) {
    asm volatile("mma.sync.aligned.m16n8k16.row.col.f32.bf16.bf16.f32 "
                 "{%0,%1,%2,%3}, {%4,%5,%6,%7}, {%8,%9}, {%0,%1,%2,%3};"
                 : "+f"(c[0]), "+f"(c[1]), "+f"(c[2]), "+f"(c[3])
                 : "r"(a[0]), "r"(a[1]), "r"(a[2]), "r"(a[3]), "r"(b[0]), "r"(b[1]));
}
__device__ __forceinline__ void split2(float v, bf16& h, bf16& l) {
    h = __float2bfloat16(v);
    l = __float2bfloat16(v - __bfloat162float(h));
}

// ---------------------------------------------------------------------------
// HMMA hi/lo GEMM: C[M,N] = Ah·Bh^T + Ah·Bl^T + Al·Bh^T  (all operands K-major)
// CTA 128x128, BK=64, 256 threads (8 warps, 4x2; warp tile 32x64), cp.async
// double buffer + ks-level fragment double buffer + term-sweep MMA order.
// EPI=0: fp32 C. EPI=1: bf16 hi/lo Ch/Cl.  grid = (N/128, M/128, batch)
// ---------------------------------------------------------------------------
#define STAGE_BYTES 65536          // 4 tiles x 16KB (Ah, Al, Bh, Bl)
#define SMEM_BYTES  (2 * STAGE_BYTES)

template <int EPI>
__global__ __launch_bounds__(256, 1)
void gemm_mma(const bf16* __restrict__ Ah, const bf16* __restrict__ Al, int lda, size_t sA,
              const bf16* __restrict__ Bh, const bf16* __restrict__ Bl, int ldb, size_t sB,
              float* __restrict__ C, bf16* __restrict__ Ch, bf16* __restrict__ Cl,
              int ldc, size_t sC, int Kd)
{
    extern __shared__ __align__(1024) char smem[];
    const uint32_t sbase = s2u(smem);

    const int tid  = threadIdx.x;
    const int lane = tid & 31;
    const int wid  = tid >> 5;
    const int wm   = wid >> 1;        // 0..3 -> m offset wm*32
    const int wn   = wid & 1;         // 0..1 -> n offset wn*64

    Ah += (size_t)blockIdx.z * sA;  Al += (size_t)blockIdx.z * sA;
    Bh += (size_t)blockIdx.z * sB;  Bl += (size_t)blockIdx.z * sB;
    if (C)  C  += (size_t)blockIdx.z * sC;
    if (Ch) Ch += (size_t)blockIdx.z * sC;
    if (Cl) Cl += (size_t)blockIdx.z * sC;
    const size_t bm = (size_t)blockIdx.y * 128;
    const size_t bn = (size_t)blockIdx.x * 128;

    const int nch = Kd >> 6;

    // per-thread swizzled gmem->smem copy offsets
    uint32_t sts_off[4];
    int g_row[4], g_ch[4];
    #pragma unroll
    for (int i = 0; i < 4; i++) {
        int idx = tid + i * 256;
        int row = idx >> 3, ch = idx & 7;
        g_row[i] = row; g_ch[i] = ch;
        sts_off[i] = (uint32_t)row * 128 + (uint32_t)((ch ^ (row & 7)) << 4);
    }

    auto load_stage = [&](int stage, int c) {
        const uint32_t so = sbase + (uint32_t)stage * STAGE_BYTES;
        const int k0 = c << 6;
        #pragma unroll
        for (int i = 0; i < 4; i++) {
            const int row = g_row[i];
            const size_t ka = (size_t)k0 + g_ch[i] * 8;
            cp16(so +          sts_off[i], Ah + (bm + row) * (size_t)lda + ka);
            cp16(so + 16384u + sts_off[i], Al + (bm + row) * (size_t)lda + ka);
            cp16(so + 32768u + sts_off[i], Bh + (bn + row) * (size_t)ldb + ka);
            cp16(so + 49152u + sts_off[i], Bl + (bn + row) * (size_t)ldb + ka);
        }
        cp_commit();
    };

    // ldmatrix per-lane address pieces
    const int lg = lane >> 3, lr = lane & 7;
    const int a_row_off = (lg & 1) * 8 + lr;   // A-op (m-major)
    const int a_ch_off  = lg >> 1;
    const int b_row_off = (lg >> 1) * 8 + lr;  // B-op (n-major)
    const int b_ch_off  = lg & 1;

    // double-buffered fragments: [buf][...]
    uint32_t ahf[2][2][4], alf[2][2][4], bhf[2][4][4], blf[2][4][4];

    auto frag_load = [&](uint32_t sb, int ks, int buf) {
        #pragma unroll
        for (int mt = 0; mt < 2; mt++) {
            const int row = wm * 32 + mt * 16 + a_row_off;
            const int ch  = 2 * ks + a_ch_off;
            const uint32_t off = (uint32_t)row * 128 + (uint32_t)(((ch ^ (row & 7)) & 7) << 4);
            ldsm4(ahf[buf][mt], sb + off);
            ldsm4(alf[buf][mt], sb + 16384u + off);
        }
        #pragma unroll
        for (int p = 0; p < 4; p++) {
            const int row = wn * 64 + p * 16 + b_row_off;
            const int ch  = 2 * ks + b_ch_off;
            const uint32_t off = (uint32_t)row * 128 + (uint32_t)(((ch ^ (row & 7)) & 7) << 4);
            ldsm4(bhf[buf][p], sb + 32768u + off);
            ldsm4(blf[buf][p], sb + 49152u + off);
        }
    };

    float acc[2][8][4];
    #pragma unroll
    for (int mt = 0; mt < 2; mt++)
        #pragma unroll
        for (int nt = 0; nt < 8; nt++)
            #pragma unroll
            for (int q = 0; q < 4; q++) acc[mt][nt][q] = 0.0f;

    // term-sweep compute: all hh, then hl, then lh -> RAW distance 16 MMAs
    auto compute = [&](int buf) {
        #pragma unroll
        for (int mt = 0; mt < 2; mt++)
            #pragma unroll
            for (int p = 0; p < 4; p++) {
                mma16816(acc[mt][2 * p],     ahf[buf][mt], &bhf[buf][p][0]);
                mma16816(acc[mt][2 * p + 1], ahf[buf][mt], &bhf[buf][p][2]);
            }
        #pragma unroll
        for (int mt = 0; mt < 2; mt++)
            #pragma unroll
            for (int p = 0; p < 4; p++) {
                mma16816(acc[mt][2 * p],     ahf[buf][mt], &blf[buf][p][0]);
                mma16816(acc[mt][2 * p + 1], ahf[buf][mt], &blf[buf][p][2]);
            }
        #pragma unroll
        for (int mt = 0; mt < 2; mt++)
            #pragma unroll
            for (int p = 0; p < 4; p++) {
                mma16816(acc[mt][2 * p],     alf[buf][mt], &bhf[buf][p][0]);
                mma16816(acc[mt][2 * p + 1], alf[buf][mt], &bhf[buf][p][2]);
            }
    };

    load_stage(0, 0);

    for (int c = 0; c < nch; c++) {
        if (c + 1 < nch) { load_stage((c + 1) & 1, c + 1); cp_wait<1>(); }
        else             { cp_wait<0>(); }
        __syncthreads();

        const uint32_t sb = sbase + (uint32_t)(c & 1) * STAGE_BYTES;
        frag_load(sb, 0, 0);
        #pragma unroll
        for (int ks = 0; ks < 4; ks++) {
            const int cur = ks & 1;
            if (ks < 3) frag_load(sb, ks + 1, cur ^ 1);   // prefetch next ks
            compute(cur);
        }
        __syncthreads();
    }

    // Epilogue: m16n8k16 acc layout: c0,c1 -> (r, c),(r, c+1); c2,c3 -> (r+8, ..)
    const int er = lane >> 2, ec = (lane & 3) * 2;
    #pragma unroll
    for (int mt = 0; mt < 2; mt++) {
        const size_t row0 = bm + wm * 32 + mt * 16 + er;
        #pragma unroll
        for (int nt = 0; nt < 8; nt++) {
            const size_t col = bn + wn * 64 + nt * 8 + ec;
            if (EPI == 0) {
                float2 v0 = make_float2(acc[mt][nt][0], acc[mt][nt][1]);
                float2 v1 = make_float2(acc[mt][nt][2], acc[mt][nt][3]);
                *(float2*)&C[row0 * ldc + col]       = v0;
                *(float2*)&C[(row0 + 8) * ldc + col] = v1;
            } else {
                bf16 h0, l0, h1, l1;
                split2(acc[mt][nt][0], h0, l0); split2(acc[mt][nt][1], h1, l1);
                *(__nv_bfloat162*)&Ch[row0 * ldc + col] = __nv_bfloat162(h0, h1);
                *(__nv_bfloat162*)&Cl[row0 * ldc + col] = __nv_bfloat162(l0, l1);
                split2(acc[mt][nt][2], h0, l0); split2(acc[mt][nt][3], h1, l1);
                *(__nv_bfloat162*)&Ch[(row0 + 8) * ldc + col] = __nv_bfloat162(h0, h1);
                *(__nv_bfloat162*)&Cl[(row0 + 8) * ldc + col] = __nv_bfloat162(l0, l1);
            }
        }
    }
}

// ---------------------------------------------------------------------------
// x fp32 -> hi/lo bf16 (elementwise, float4)
// ---------------------------------------------------------------------------
__global__ __launch_bounds__(256)
void convert_split(const float4* __restrict__ in, uint2* __restrict__ oh, uint2* __restrict__ ol)
{
    const size_t i = (size_t)blockIdx.x * 256 + threadIdx.x;
    float4 v = in[i];
    bf16 h[4], l[4];
    split2(v.x, h[0], l[0]); split2(v.y, h[1], l[1]);
    split2(v.z, h[2], l[2]); split2(v.w, h[3], l[3]);
    oh[i] = *(uint2*)h;  ol[i] = *(uint2*)l;
}

// ---------------------------------------------------------------------------
// W [512,512] -> W^T hi/lo bf16 (tiled transpose)
// ---------------------------------------------------------------------------
__global__ __launch_bounds__(256)
void wtrans(const float* __restrict__ W, bf16* __restrict__ Th, bf16* __restrict__ Tl)
{
    __shared__ float t[32][33];
    const int bx = blockIdx.x * 32, by = blockIdx.y * 32;
    const int tx = threadIdx.x, ty = threadIdx.y;
    #pragma unroll
    for (int i = ty; i < 32; i += 8)
        t[i][tx] = W[(size_t)(by + i) * DIM + bx + tx];
    __syncthreads();
    #pragma unroll
    for (int i = ty; i < 32; i += 8) {
        float v = t[tx][i];                               // = W[by+tx][bx+i]
        bf16 h, l; split2(v, h, l);
        Th[(size_t)(bx + i) * DIM + by + tx] = h;         // W^T
        Tl[(size_t)(bx + i) * DIM + by + tx] = l;
    }
}

// ---------------------------------------------------------------------------
// Row softmax of P (fp32) -> hi/lo bf16. One block per row (2048 cols).
// ---------------------------------------------------------------------------
__global__ __launch_bounds__(256)
void softmax_split(const float* __restrict__ P, bf16* __restrict__ Ph, bf16* __restrict__ Pl)
{
    const float* p = P + (size_t)blockIdx.x * SEQ;
    const int tid = threadIdx.x;
    __shared__ float red[8];

    float4 a = *(const float4*)&p[tid * 4];
    float4 b = *(const float4*)&p[1024 + tid * 4];
    float v[8] = {a.x, a.y, a.z, a.w, b.x, b.y, b.z, b.w};

    float m = v[0];
    #pragma unroll
    for (int i = 1; i < 8; i++) m = fmaxf(m, v[i]);
    #pragma unroll
    for (int o = 16; o > 0; o >>= 1) m = fmaxf(m, __shfl_xor_sync(~0u, m, o));
    if ((tid & 31) == 0) red[tid >> 5] = m;
    __syncthreads();
    m = red[0];
    #pragma unroll
    for (int i = 1; i < 8; i++) m = fmaxf(m, red[i]);
    __syncthreads();

    const float sc = 0.044194173824159216f;   // 1/sqrt(512)
    float s = 0.0f;
    #pragma unroll
    for (int i = 0; i < 8; i++) { v[i] = __expf((v[i] - m) * sc); s += v[i]; }
    #pragma unroll
    for (int o = 16; o > 0; o >>= 1) s += __shfl_xor_sync(~0u, s, o);
    if ((tid & 31) == 0) red[tid >> 5] = s;
    __syncthreads();
    s = 0.0f;
    #pragma unroll
    for (int i = 0; i < 8; i++) s += red[i];
    const float rinv = 1.0f / s;

    bf16 h[8], l[8];
    #pragma unroll
    for (int i = 0; i < 8; i++) split2(v[i] * rinv, h[i], l[i]);
    const size_t base = (size_t)blockIdx.x * SEQ;
    *(uint2*)&Ph[base + tid * 4]        = *(uint2*)&h[0];
    *(uint2*)&Ph[base + 1024 + tid * 4] = *(uint2*)&h[4];
    *(uint2*)&Pl[base + tid * 4]        = *(uint2*)&l[0];
    *(uint2*)&Pl[base + 1024 + tid * 4] = *(uint2*)&l[4];
}

// ---------------------------------------------------------------------------
extern "C" void kernel_launch(void* const* d_in, const int* in_sizes, int n_in,
                              void* d_out, int out_size)
{
    const float* x  = (const float*)d_in[0];
    const float* Wq = (const float*)d_in[1];
    const float* Wk = (const float*)d_in[2];
    const float* Wv = (const float*)d_in[3];
    float* out = (float*)d_out;

    bf16 *Xh, *Xl, *WTh, *WTl, *Qh, *Ql, *Kh, *Kl, *Vth, *Vtl, *Ph, *Pl;
    float* P;
    cudaGetSymbolAddress((void**)&Xh, g_Xh);   cudaGetSymbolAddress((void**)&Xl, g_Xl);
    cudaGetSymbolAddress((void**)&WTh, g_WTh); cudaGetSymbolAddress((void**)&WTl, g_WTl);
    cudaGetSymbolAddress((void**)&Qh, g_Qh);   cudaGetSymbolAddress((void**)&Ql, g_Ql);
    cudaGetSymbolAddress((void**)&Kh, g_Kh);   cudaGetSymbolAddress((void**)&Kl, g_Kl);
    cudaGetSymbolAddress((void**)&Vth, g_Vth); cudaGetSymbolAddress((void**)&Vtl, g_Vtl);
    cudaGetSymbolAddress((void**)&P, g_P);
    cudaGetSymbolAddress((void**)&Ph, g_Ph);   cudaGetSymbolAddress((void**)&Pl, g_Pl);

    cudaFuncSetAttribute(gemm_mma<0>, cudaFuncAttributeMaxDynamicSharedMemorySize, SMEM_BYTES);
    cudaFuncSetAttribute(gemm_mma<1>, cudaFuncAttributeMaxDynamicSharedMemorySize, SMEM_BYTES);

    // hi/lo conversions
    convert_split<<<(TOK * DIM) / 1024, 256>>>((const float4*)x, (uint2*)Xh, (uint2*)Xl);
    wtrans<<<dim3(16, 16), dim3(32, 8)>>>(Wq, WTh + 0 * DIM * DIM, WTl + 0 * DIM * DIM);
    wtrans<<<dim3(16, 16), dim3(32, 8)>>>(Wk, WTh + 1 * DIM * DIM, WTl + 1 * DIM * DIM);
    wtrans<<<dim3(16, 16), dim3(32, 8)>>>(Wv, WTh + 2 * DIM * DIM, WTl + 2 * DIM * DIM);

    // Q = X @ Wq  (bf16 hi/lo out)
    gemm_mma<1><<<dim3(4, 128, 1), 256, SMEM_BYTES>>>(
        Xh, Xl, DIM, 0, WTh, WTl, DIM, 0,
        nullptr, Qh, Ql, DIM, 0, DIM);
    // K = X @ Wk
    gemm_mma<1><<<dim3(4, 128, 1), 256, SMEM_BYTES>>>(
        Xh, Xl, DIM, 0, WTh + DIM * DIM, WTl + DIM * DIM, DIM, 0,
        nullptr, Kh, Kl, DIM, 0, DIM);
    // V^T[e, tok] = sum_d Wv^T[e,d] * X[tok,d]
    gemm_mma<1><<<dim3(128, 4, 1), 256, SMEM_BYTES>>>(
        WTh + 2 * DIM * DIM, WTl + 2 * DIM * DIM, DIM, 0, Xh, Xl, DIM, 0,
        nullptr, Vth, Vtl, TOK, 0, DIM);

    // P[b] = Q[b] @ K[b]^T  (fp32 out)
    gemm_mma<0><<<dim3(16, 16, BATCH), 256, SMEM_BYTES>>>(
        Qh, Ql, DIM, (size_t)SEQ * DIM, Kh, Kl, DIM, (size_t)SEQ * DIM,
        P, nullptr, nullptr, SEQ, (size_t)SEQ * SEQ, DIM);

    // softmax rows + split to bf16 hi/lo
    softmax_split<<<BATCH * SEQ, 256>>>(P, Ph, Pl);

    // out[b] = P[b] @ V[b]  via B = V^T (ldb = TOK, batch column offset)
    gemm_mma<0><<<dim3(4, 16, BATCH), 256, SMEM_BYTES>>>(
        Ph, Pl, SEQ, (size_t)SEQ * SEQ, Vth, Vtl, TOK, (size_t)SEQ,
        out, nullptr, nullptr, DIM, (size_t)SEQ * DIM, SEQ);
}

// round 6
// speedup vs baseline: 1.0966x; 1.0966x over previous
#include <cuda_runtime.h>
#include <cuda_bf16.h>
#include <cstdint>

#define BATCH 8
#define SEQ   2048
#define DIM   512
#define TOK   (BATCH*SEQ)          // 16384

typedef __nv_bfloat16 bf16;

// ---------------------------------------------------------------------------
// Scratch (__device__ globals: allocation-guard safe)
// ---------------------------------------------------------------------------
__device__ bf16  g_Xh[(size_t)TOK * DIM],  g_Xl[(size_t)TOK * DIM];
__device__ bf16  g_WTh[3][DIM * DIM],      g_WTl[3][DIM * DIM];   // W^T hi/lo
__device__ bf16  g_QKh[2][(size_t)TOK * DIM], g_QKl[2][(size_t)TOK * DIM]; // Q=0, K=1
__device__ bf16  g_Vth[(size_t)DIM * TOK], g_Vtl[(size_t)DIM * TOK]; // V^T [512,16384]
__device__ float g_P [(size_t)BATCH * SEQ * SEQ];
__device__ bf16  g_Ph[(size_t)BATCH * SEQ * SEQ], g_Pl[(size_t)BATCH * SEQ * SEQ];

// ---------------------------------------------------------------------------
// Baseline-PTX helpers (sm_80+: valid for compute_103 target)
// ---------------------------------------------------------------------------
__device__ __forceinline__ uint32_t s2u(const void* p) {
    uint32_t a;
    asm("{ .reg .u64 t; cvta.to.shared.u64 t, %1; cvt.u32.u64 %0, t; }" : "=r"(a) : "l"(p));
    return a;
}
__device__ __forceinline__ void cp16(uint32_t saddr, const bf16* g) {
    asm volatile("cp.async.cg.shared.global [%0], [%1], 16;"
                 :: "r"(saddr), "l"(__cvta_generic_to_global(g)) : "memory");
}
__device__ __forceinline__ void cp_commit() {
    asm volatile("cp.async.commit_group;" ::: "memory");
}
template <int N>
__device__ __forceinline__ void cp_wait() {
    asm volatile("cp.async.wait_group %0;" :: "n"(N) : "memory");
}
__device__ __forceinline__ void ldsm4(uint32_t* d, uint32_t a) {
    asm volatile("ldmatrix.sync.aligned.m8n8.x4.shared.b16 {%0,%1,%2,%3}, [%4];"
                 : "=r"(d[0]), "=r"(d[1]), "=r"(d[2]), "=r"(d[3]) : "r"(a));
}
__device__ __forceinline__ void mma16816(float* c, const uint32_t* a, const uint32_t* b) {
    asm volatile("mma.sync.aligned.m16n8k16.row.col.f32.bf16.bf16.f32 "
                 "{%0,%1,%2,%3}, {%4,%5,%6,%7}, {%8,%9}, {%0,%1,%2,%3};"
                 : "+f"(c[0]), "+f"(c[1]), "+f"(c[2]), "+f"(c[3])
                 : "r"(a[0]), "r"(a[1]), "r"(a[2]), "r"(a[3]), "r"(b[0]), "r"(b[1]));
}
__device__ __forceinline__ void split2(float v, bf16& h, bf16& l) {
    h = __float2bfloat16(v);
    l = __float2bfloat16(v - __bfloat162float(h));
}

// ---------------------------------------------------------------------------
// HMMA hi/lo GEMM: C[M,N] = Ah·Bh^T + Ah·Bl^T + Al·Bh^T  (all operands K-major)
// CTA 128x128, BK=32, 256 threads (8 warps 4x2, warp tile 32x64), 3-stage
// cp.async pipeline, 2 CTAs/SM.  EPI=0: fp32 C. EPI=1: bf16 hi/lo Ch/Cl.
// grid = (N/128, M/128, batch)
// ---------------------------------------------------------------------------
#define STAGE_BYTES 32768          // 4 tiles x 8KB (Ah, Al, Bh, Bl), 128 rows x 64B
#define NSTAGE      3
#define SMEM_BYTES  (NSTAGE * STAGE_BYTES)

template <int EPI>
__global__ __launch_bounds__(256, 2)
void gemm_mma(const bf16* __restrict__ Ah, const bf16* __restrict__ Al, int lda, size_t sA,
              const bf16* __restrict__ Bh, const bf16* __restrict__ Bl, int ldb, size_t sB,
              float* __restrict__ C, bf16* __restrict__ Ch, bf16* __restrict__ Cl,
              int ldc, size_t sC, int Kd)
{
    extern __shared__ __align__(1024) char smem[];
    const uint32_t sbase = s2u(smem);

    const int tid  = threadIdx.x;
    const int lane = tid & 31;
    const int wid  = tid >> 5;
    const int wm   = wid >> 1;        // 0..3 -> m offset wm*32
    const int wn   = wid & 1;         // 0..1 -> n offset wn*64

    Ah += (size_t)blockIdx.z * sA;  Al += (size_t)blockIdx.z * sA;
    Bh += (size_t)blockIdx.z * sB;  Bl += (size_t)blockIdx.z * sB;
    if (C)  C  += (size_t)blockIdx.z * sC;
    if (Ch) Ch += (size_t)blockIdx.z * sC;
    if (Cl) Cl += (size_t)blockIdx.z * sC;
    const size_t bm = (size_t)blockIdx.y * 128;
    const size_t bn = (size_t)blockIdx.x * 128;

    const int nch = Kd >> 5;          // chunks of 32

    // gmem->smem copy: per tile 512 chunks of 16B; thread handles rows r0, r0+64
    // at chunk ch.  Swizzle: xch = ch ^ ((row>>1)&3); (row+64) keeps same xch.
    const int cr0 = tid >> 2;          // 0..63
    const int cch = tid & 3;
    const uint32_t s0 = (uint32_t)cr0 * 64 + (uint32_t)((cch ^ ((cr0 >> 1) & 3)) << 4);

    auto load_stage = [&](int stage, int c) {
        const uint32_t so = sbase + (uint32_t)stage * STAGE_BYTES;
        const size_t ka = (size_t)(c << 5) + cch * 8;
        const bf16* a_h = Ah + (bm + cr0) * (size_t)lda + ka;
        const bf16* a_l = Al + (bm + cr0) * (size_t)lda + ka;
        const bf16* b_h = Bh + (bn + cr0) * (size_t)ldb + ka;
        const bf16* b_l = Bl + (bn + cr0) * (size_t)ldb + ka;
        const size_t r64a = (size_t)64 * lda, r64b = (size_t)64 * ldb;
        cp16(so +          s0,         a_h);
        cp16(so +          s0 + 4096u, a_h + r64a);
        cp16(so +  8192u + s0,         a_l);
        cp16(so +  8192u + s0 + 4096u, a_l + r64a);
        cp16(so + 16384u + s0,         b_h);
        cp16(so + 16384u + s0 + 4096u, b_h + r64b);
        cp16(so + 24576u + s0,         b_l);
        cp16(so + 24576u + s0 + 4096u, b_l + r64b);
        cp_commit();
    };

    // ldmatrix per-lane pieces
    const int lg = lane >> 3, lr = lane & 7;
    const int a_row_off = (lg & 1) * 8 + lr;   // A-op (m-major)
    const int a_ch_off  = lg >> 1;
    const int b_row_off = (lg >> 1) * 8 + lr;  // B-op (n-major)
    const int b_ch_off  = lg & 1;

    uint32_t ahf[2][4], alf[2][4], bhf[4][4], blf[4][4];

    auto frag_load = [&](uint32_t sb, int ks) {
        #pragma unroll
        for (int mt = 0; mt < 2; mt++) {
            const int row = wm * 32 + mt * 16 + a_row_off;
            const int ch  = 2 * ks + a_ch_off;
            const uint32_t off = (uint32_t)row * 64 + (uint32_t)(((ch ^ ((row >> 1) & 3)) & 3) << 4);
            ldsm4(ahf[mt], sb + off);
            ldsm4(alf[mt], sb + 8192u + off);
        }
        #pragma unroll
        for (int p = 0; p < 4; p++) {
            const int row = wn * 64 + p * 16 + b_row_off;
            const int ch  = 2 * ks + b_ch_off;
            const uint32_t off = (uint32_t)row * 64 + (uint32_t)(((ch ^ ((row >> 1) & 3)) & 3) << 4);
            ldsm4(bhf[p], sb + 16384u + off);
            ldsm4(blf[p], sb + 24576u + off);
        }
    };

    float acc[2][8][4];
    #pragma unroll
    for (int mt = 0; mt < 2; mt++)
        #pragma unroll
        for (int nt = 0; nt < 8; nt++)
            #pragma unroll
            for (int q = 0; q < 4; q++) acc[mt][nt][q] = 0.0f;

    auto compute = [&]() {
        #pragma unroll
        for (int mt = 0; mt < 2; mt++)
            #pragma unroll
            for (int p = 0; p < 4; p++) {
                mma16816(acc[mt][2 * p],     ahf[mt], &bhf[p][0]);
                mma16816(acc[mt][2 * p + 1], ahf[mt], &bhf[p][2]);
            }
        #pragma unroll
        for (int mt = 0; mt < 2; mt++)
            #pragma unroll
            for (int p = 0; p < 4; p++) {
                mma16816(acc[mt][2 * p],     ahf[mt], &blf[p][0]);
                mma16816(acc[mt][2 * p + 1], ahf[mt], &blf[p][2]);
            }
        #pragma unroll
        for (int mt = 0; mt < 2; mt++)
            #pragma unroll
            for (int p = 0; p < 4; p++) {
                mma16816(acc[mt][2 * p],     alf[mt], &bhf[p][0]);
                mma16816(acc[mt][2 * p + 1], alf[mt], &bhf[p][2]);
            }
    };

    // 3-stage pipeline prologue: stages 0,1 in flight
    load_stage(0, 0);
    load_stage(1, 1);

    int slot = 0;
    for (int c = 0; c < nch; c++) {
        if (c + 1 < nch) cp_wait<1>(); else cp_wait<0>();
        __syncthreads();

        const uint32_t sb = sbase + (uint32_t)slot * STAGE_BYTES;
        frag_load(sb, 0);
        compute();
        frag_load(sb, 1);
        compute();

        if (c + 2 < nch) {
            int nslot = slot + 2; if (nslot >= NSTAGE) nslot -= NSTAGE;
            load_stage(nslot, c + 2);
        }
        if (++slot == NSTAGE) slot = 0;
    }

    // Epilogue: m16n8k16 acc: c0,c1 -> (r, c),(r, c+1); c2,c3 -> (r+8, ..)
    const int er = lane >> 2, ec = (lane & 3) * 2;
    #pragma unroll
    for (int mt = 0; mt < 2; mt++) {
        const size_t row0 = bm + wm * 32 + mt * 16 + er;
        #pragma unroll
        for (int nt = 0; nt < 8; nt++) {
            const size_t col = bn + wn * 64 + nt * 8 + ec;
            if (EPI == 0) {
                float2 v0 = make_float2(acc[mt][nt][0], acc[mt][nt][1]);
                float2 v1 = make_float2(acc[mt][nt][2], acc[mt][nt][3]);
                *(float2*)&C[row0 * ldc + col]       = v0;
                *(float2*)&C[(row0 + 8) * ldc + col] = v1;
            } else {
                bf16 h0, l0, h1, l1;
                split2(acc[mt][nt][0], h0, l0); split2(acc[mt][nt][1], h1, l1);
                *(__nv_bfloat162*)&Ch[row0 * ldc + col] = __nv_bfloat162(h0, h1);
                *(__nv_bfloat162*)&Cl[row0 * ldc + col] = __nv_bfloat162(l0, l1);
                split2(acc[mt][nt][2], h0, l0); split2(acc[mt][nt][3], h1, l1);
                *(__nv_bfloat162*)&Ch[(row0 + 8) * ldc + col] = __nv_bfloat162(h0, h1);
                *(__nv_bfloat162*)&Cl[(row0 + 8) * ldc + col] = __nv_bfloat162(l0, l1);
            }
        }
    }
}

// ---------------------------------------------------------------------------
// x fp32 -> hi/lo bf16 (elementwise, float4)
// ---------------------------------------------------------------------------
__global__ __launch_bounds__(256)
void convert_split(const float4* __restrict__ in, uint2* __restrict__ oh, uint2* __restrict__ ol)
{
    const size_t i = (size_t)blockIdx.x * 256 + threadIdx.x;
    float4 v = in[i];
    bf16 h[4], l[4];
    split2(v.x, h[0], l[0]); split2(v.y, h[1], l[1]);
    split2(v.z, h[2], l[2]); split2(v.w, h[3], l[3]);
    oh[i] = *(uint2*)h;  ol[i] = *(uint2*)l;
}

// ---------------------------------------------------------------------------
// W [512,512] -> W^T hi/lo bf16 (tiled transpose)
// ---------------------------------------------------------------------------
__global__ __launch_bounds__(256)
void wtrans(const float* __restrict__ W, bf16* __restrict__ Th, bf16* __restrict__ Tl)
{
    __shared__ float t[32][33];
    const int bx = blockIdx.x * 32, by = blockIdx.y * 32;
    const int tx = threadIdx.x, ty = threadIdx.y;
    #pragma unroll
    for (int i = ty; i < 32; i += 8)
        t[i][tx] = W[(size_t)(by + i) * DIM + bx + tx];
    __syncthreads();
    #pragma unroll
    for (int i = ty; i < 32; i += 8) {
        float v = t[tx][i];                               // = W[by+tx][bx+i]
        bf16 h, l; split2(v, h, l);
        Th[(size_t)(bx + i) * DIM + by + tx] = h;         // W^T
        Tl[(size_t)(bx + i) * DIM + by + tx] = l;
    }
}

// ---------------------------------------------------------------------------
// Row softmax of P (fp32) -> hi/lo bf16. One block per row (2048 cols).
// ---------------------------------------------------------------------------
__global__ __launch_bounds__(256)
void softmax_split(const float* __restrict__ P, bf16* __restrict__ Ph, bf16* __restrict__ Pl)
{
    const float* p = P + (size_t)blockIdx.x * SEQ;
    const int tid = threadIdx.x;
    __shared__ float red[8];

    float4 a = *(const float4*)&p[tid * 4];
    float4 b = *(const float4*)&p[1024 + tid * 4];
    float v[8] = {a.x, a.y, a.z, a.w, b.x, b.y, b.z, b.w};

    float m = v[0];
    #pragma unroll
    for (int i = 1; i < 8; i++) m = fmaxf(m, v[i]);
    #pragma unroll
    for (int o = 16; o > 0; o >>= 1) m = fmaxf(m, __shfl_xor_sync(~0u, m, o));
    if ((tid & 31) == 0) red[tid >> 5] = m;
    __syncthreads();
    m = red[0];
    #pragma unroll
    for (int i = 1; i < 8; i++) m = fmaxf(m, red[i]);
    __syncthreads();

    const float sc = 0.044194173824159216f;   // 1/sqrt(512)
    float s = 0.0f;
    #pragma unroll
    for (int i = 0; i < 8; i++) { v[i] = __expf((v[i] - m) * sc); s += v[i]; }
    #pragma unroll
    for (int o = 16; o > 0; o >>= 1) s += __shfl_xor_sync(~0u, s, o);
    if ((tid & 31) == 0) red[tid >> 5] = s;
    __syncthreads();
    s = 0.0f;
    #pragma unroll
    for (int i = 0; i < 8; i++) s += red[i];
    const float rinv = 1.0f / s;

    bf16 h[8], l[8];
    #pragma unroll
    for (int i = 0; i < 8; i++) split2(v[i] * rinv, h[i], l[i]);
    const size_t base = (size_t)blockIdx.x * SEQ;
    *(uint2*)&Ph[base + tid * 4]        = *(uint2*)&h[0];
    *(uint2*)&Ph[base + 1024 + tid * 4] = *(uint2*)&h[4];
    *(uint2*)&Pl[base + tid * 4]        = *(uint2*)&l[0];
    *(uint2*)&Pl[base + 1024 + tid * 4] = *(uint2*)&l[4];
}

// ---------------------------------------------------------------------------
extern "C" void kernel_launch(void* const* d_in, const int* in_sizes, int n_in,
                              void* d_out, int out_size)
{
    const float* x  = (const float*)d_in[0];
    const float* Wq = (const float*)d_in[1];
    const float* Wk = (const float*)d_in[2];
    const float* Wv = (const float*)d_in[3];
    float* out = (float*)d_out;

    bf16 *Xh, *Xl, *WTh, *WTl, *QKh, *QKl, *Vth, *Vtl, *Ph, *Pl;
    float* P;
    cudaGetSymbolAddress((void**)&Xh, g_Xh);   cudaGetSymbolAddress((void**)&Xl, g_Xl);
    cudaGetSymbolAddress((void**)&WTh, g_WTh); cudaGetSymbolAddress((void**)&WTl, g_WTl);
    cudaGetSymbolAddress((void**)&QKh, g_QKh); cudaGetSymbolAddress((void**)&QKl, g_QKl);
    cudaGetSymbolAddress((void**)&Vth, g_Vth); cudaGetSymbolAddress((void**)&Vtl, g_Vtl);
    cudaGetSymbolAddress((void**)&P, g_P);
    cudaGetSymbolAddress((void**)&Ph, g_Ph);   cudaGetSymbolAddress((void**)&Pl, g_Pl);

    const size_t QK = (size_t)TOK * DIM;

    cudaFuncSetAttribute(gemm_mma<0>, cudaFuncAttributeMaxDynamicSharedMemorySize, SMEM_BYTES);
    cudaFuncSetAttribute(gemm_mma<1>, cudaFuncAttributeMaxDynamicSharedMemorySize, SMEM_BYTES);

    // hi/lo conversions
    convert_split<<<(TOK * DIM) / 1024, 256>>>((const float4*)x, (uint2*)Xh, (uint2*)Xl);
    wtrans<<<dim3(16, 16), dim3(32, 8)>>>(Wq, WTh + 0 * DIM * DIM, WTl + 0 * DIM * DIM);
    wtrans<<<dim3(16, 16), dim3(32, 8)>>>(Wk, WTh + 1 * DIM * DIM, WTl + 1 * DIM * DIM);
    wtrans<<<dim3(16, 16), dim3(32, 8)>>>(Wv, WTh + 2 * DIM * DIM, WTl + 2 * DIM * DIM);

    // Q and K projections in ONE launch: z=0 -> Q (Wq), z=1 -> K (Wk)
    gemm_mma<1><<<dim3(4, 128, 2), 256, SMEM_BYTES>>>(
        Xh, Xl, DIM, 0, WTh, WTl, DIM, (size_t)DIM * DIM,
        nullptr, QKh, QKl, DIM, QK, DIM);
    // V^T[e, tok] = sum_d Wv^T[e,d] * X[tok,d]
    gemm_mma<1><<<dim3(128, 4, 1), 256, SMEM_BYTES>>>(
        WTh + 2 * DIM * DIM, WTl + 2 * DIM * DIM, DIM, 0, Xh, Xl, DIM, 0,
        nullptr, Vth, Vtl, TOK, 0, DIM);

    // P[b] = Q[b] @ K[b]^T  (fp32 out)
    gemm_mma<0><<<dim3(16, 16, BATCH), 256, SMEM_BYTES>>>(
        QKh, QKl, DIM, (size_t)SEQ * DIM, QKh + QK, QKl + QK, DIM, (size_t)SEQ * DIM,
        P, nullptr, nullptr, SEQ, (size_t)SEQ * SEQ, DIM);

    // softmax rows + split to bf16 hi/lo
    softmax_split<<<BATCH * SEQ, 256>>>(P, Ph, Pl);

    // out[b] = P[b] @ V[b]  via B = V^T (ldb = TOK, batch column offset)
    gemm_mma<0><<<dim3(4, 16, BATCH), 256, SMEM_BYTES>>>(
        Ph, Pl, SEQ, (size_t)SEQ * SEQ, Vth, Vtl, TOK, (size_t)SEQ,
        out, nullptr, nullptr, DIM, (size_t)SEQ * DIM, SEQ);
}